// round 13
// baseline (speedup 1.0000x reference)
#include <cuda_runtime.h>
#include <math.h>
#include <stdint.h>

#define NTOK 1024
#define LL   32
#define DD   768
#define IND  64
#define NOUT 16
#define OUTD 64
#define EPSF 1e-8f

__device__ float g_mu[(size_t)LL * NTOK * IND];        // [l][n][i]
__device__ float g_f[LL * NTOK];                       // [l][n]
__device__ float g_V[(size_t)NTOK * LL * NOUT * OUTD]; // [n][l][k][o]

__device__ __forceinline__ float tf32r(float x) {
    uint32_t o;
    asm("cvt.rn.tf32.f32 %0, %1;" : "=r"(o) : "f"(x));
    return __uint_as_float(o);
}
__device__ __forceinline__ void mma8(float c[4], uint32_t a0, uint32_t a1,
                                     uint32_t a2, uint32_t a3,
                                     uint32_t b0, uint32_t b1) {
    asm("mma.sync.aligned.m16n8k8.row.col.f32.tf32.tf32.f32 "
        "{%0,%1,%2,%3}, {%4,%5,%6,%7}, {%8,%9}, {%0,%1,%2,%3};"
        : "+f"(c[0]), "+f"(c[1]), "+f"(c[2]), "+f"(c[3])
        : "r"(a0), "r"(a1), "r"(a2), "r"(a3), "r"(b0), "r"(b1));
}
// 3-pass compensated mma from (hi,lo) float2 fragments
__device__ __forceinline__ void mma3(float c[4], const float2 a0, const float2 a1,
                                     const float2 a2, const float2 a3,
                                     const float2 b0, const float2 b1) {
    uint32_t ah0 = __float_as_uint(a0.x), al0 = __float_as_uint(a0.y);
    uint32_t ah1 = __float_as_uint(a1.x), al1 = __float_as_uint(a1.y);
    uint32_t ah2 = __float_as_uint(a2.x), al2 = __float_as_uint(a2.y);
    uint32_t ah3 = __float_as_uint(a3.x), al3 = __float_as_uint(a3.y);
    uint32_t bh0 = __float_as_uint(b0.x), bl0 = __float_as_uint(b0.y);
    uint32_t bh1 = __float_as_uint(b1.x), bl1 = __float_as_uint(b1.y);
    mma8(c, al0, al1, al2, al3, bh0, bh1);
    mma8(c, ah0, ah1, ah2, ah3, bl0, bl1);
    mma8(c, ah0, ah1, ah2, ah3, bh0, bh1);
}
__device__ __forceinline__ float2 hl(float v) {
    float h = tf32r(v);
    return make_float2(h, tf32r(v - h));
}
__device__ __forceinline__ float gelu(float v) {
    return 0.5f * v * (1.0f + erff(v * 0.70710678118654752f));
}
__device__ __forceinline__ float wred(float v) {
#pragma unroll
    for (int o = 16; o; o >>= 1) v += __shfl_xor_sync(0xffffffffu, v, o);
    return v;
}

// Single shared-memory base used by all kernels (avoids multi-type extern decls)
extern __shared__ __align__(16) unsigned char smbase[];

// ---------------------------------------------------------------------------
// K1: per (l, 128-token tile). Block 256 (8 warps), warp = M32 x N32.
// SMEM holds (hi,lo) float2 pairs; mainloop = pure LDS.64 + MMA.
// 48 K-chunks of 16, double-buffered, 1 sync/chunk.
// ---------------------------------------------------------------------------
#define AP 28   // A2 row stride (float2): 16 k + 12 pad -> frag conflict-free
#define BP 68   // B2 row stride (float2): 64 n + 4 pad
#define K1_F2 (2 * 128 * AP + 2 * 16 * BP)
#define K1_DYN (K1_F2 * 8 + (32 + 64 + 256) * 4)
__global__ __launch_bounds__(256) void k1h(
    const float* __restrict__ x, const float* __restrict__ mask,
    const float* __restrict__ Wscore, const float* __restrict__ Bscore,
    const float* __restrict__ Wcap, const float* __restrict__ Bcap) {
    float2* A2 = (float2*)smbase;                     // [2][128][AP]
    float2* B2 = A2 + 2 * 128 * AP;                   // [2][16][BP]
    float*  Ws  = (float*)(smbase + K1_F2 * 8);       // [2][16]
    float*  bcs = Ws + 32;                            // [64]
    float*  sred = bcs + 64;                          // [256]

    const int l = blockIdx.y, n0 = blockIdx.x * 128;
    const int tid = threadIdx.x, wid = tid >> 5, lane = tid & 31;
    const int g = lane >> 2, tig = lane & 3;
    const int wm = wid & 3, wn = wid >> 2;       // warp tile: M32 (wm), N32 (wn)
    const int am = tid & 127, ah8 = (tid >> 7) * 8;   // A staging: row, k-offset
    const int bk = tid >> 4, bi = tid & 15;           // B staging: k-row, n-base

    if (tid < 64) bcs[tid] = Bcap[l * IND + tid];

    const float* xl = x + (size_t)(n0 + am) * (LL * DD) + (size_t)l * DD + ah8;
    const float* wc = Wcap + (size_t)l * DD * IND;

    float av[8];
    float bv[4];
    float w_st = 0.0f;
    // load chunk 0
    {
        float4 t0 = *(const float4*)(xl), t1 = *(const float4*)(xl + 4);
        av[0] = t0.x; av[1] = t0.y; av[2] = t0.z; av[3] = t0.w;
        av[4] = t1.x; av[5] = t1.y; av[6] = t1.z; av[7] = t1.w;
#pragma unroll
        for (int j = 0; j < 4; j++) bv[j] = wc[(size_t)bk * IND + bi + 16 * j];
        if (tid < 16) w_st = Wscore[l * DD + tid];
    }
    // store chunk 0 into buffer 0
    {
        float2* Ar = A2 + am * AP + ah8;
#pragma unroll
        for (int j = 0; j < 4; j++) {
            float2 p0 = hl(av[2 * j]), p1 = hl(av[2 * j + 1]);
            *(float4*)(Ar + 2 * j) = make_float4(p0.x, p0.y, p1.x, p1.y);
        }
        float2* Br = B2 + bk * BP + bi;
#pragma unroll
        for (int j = 0; j < 4; j++) Br[16 * j] = hl(bv[j]);
        if (tid < 16) Ws[tid] = w_st;
    }
    __syncthreads();

    float acc[2][4][4] = {};
    float sacc = 0.0f;

    for (int c = 0; c < 48; c++) {
        const int buf = c & 1;
        const float* Wb = Ws + buf * 16;
        // score partial from full-fp32 regs of chunk c
        {
#pragma unroll
            for (int j = 0; j < 8; j++) sacc = fmaf(av[j], Wb[ah8 + j], sacc);
        }
        // prefetch chunk c+1
        if (c + 1 < 48) {
            int k0 = (c + 1) * 16;
            float4 t0 = *(const float4*)(xl + k0), t1 = *(const float4*)(xl + k0 + 4);
            av[0] = t0.x; av[1] = t0.y; av[2] = t0.z; av[3] = t0.w;
            av[4] = t1.x; av[5] = t1.y; av[6] = t1.z; av[7] = t1.w;
#pragma unroll
            for (int j = 0; j < 4; j++) bv[j] = wc[(size_t)(k0 + bk) * IND + bi + 16 * j];
            if (tid < 16) w_st = Wscore[l * DD + k0 + tid];
        }
        // mma on buffer buf: 2 k8 steps
        const float2* Ab = A2 + buf * (128 * AP);
        const float2* Bb = B2 + buf * (16 * BP);
#pragma unroll
        for (int ks = 0; ks < 2; ks++) {
            const int kk = ks * 8;
            float2 af[2][4];
#pragma unroll
            for (int mf = 0; mf < 2; mf++) {
                int r = wm * 32 + mf * 16;
                af[mf][0] = Ab[(r + g) * AP + kk + tig];
                af[mf][1] = Ab[(r + g + 8) * AP + kk + tig];
                af[mf][2] = Ab[(r + g) * AP + kk + tig + 4];
                af[mf][3] = Ab[(r + g + 8) * AP + kk + tig + 4];
            }
#pragma unroll
            for (int nt = 0; nt < 4; nt++) {
                int n = wn * 32 + nt * 8 + g;
                float2 q0 = Bb[(kk + tig) * BP + n];
                float2 q1 = Bb[(kk + tig + 4) * BP + n];
#pragma unroll
                for (int mf = 0; mf < 2; mf++)
                    mma3(acc[mf][nt], af[mf][0], af[mf][1], af[mf][2], af[mf][3], q0, q1);
            }
        }
        // store chunk c+1 into the other buffer
        if (c + 1 < 48) {
            const int nb = buf ^ 1;
            float2* Ar = A2 + nb * (128 * AP) + am * AP + ah8;
#pragma unroll
            for (int j = 0; j < 4; j++) {
                float2 p0 = hl(av[2 * j]), p1 = hl(av[2 * j + 1]);
                *(float4*)(Ar + 2 * j) = make_float4(p0.x, p0.y, p1.x, p1.y);
            }
            float2* Br = B2 + nb * (16 * BP) + bk * BP + bi;
#pragma unroll
            for (int j = 0; j < 4; j++) Br[16 * j] = hl(bv[j]);
            if (tid < 16) Ws[nb * 16 + tid] = w_st;
        }
        __syncthreads();
    }
    // epilogue: bias + GELU -> g_mu
#pragma unroll
    for (int mf = 0; mf < 2; mf++) {
        int r0 = wm * 32 + mf * 16 + g;
#pragma unroll
        for (int nt = 0; nt < 4; nt++) {
            int col = wn * 32 + nt * 8 + 2 * tig;
            float b0v = bcs[col], b1v = bcs[col + 1];
            float2 v0, v1;
            v0.x = gelu(acc[mf][nt][0] + b0v);
            v0.y = gelu(acc[mf][nt][1] + b1v);
            v1.x = gelu(acc[mf][nt][2] + b0v);
            v1.y = gelu(acc[mf][nt][3] + b1v);
            *(float2*)(g_mu + ((size_t)l * NTOK + n0 + r0) * IND + col) = v0;
            *(float2*)(g_mu + ((size_t)l * NTOK + n0 + r0 + 8) * IND + col) = v1;
        }
    }
    // score: combine the two k-half partials
    sred[tid] = sacc;
    __syncthreads();
    if (tid < 128) {
        int n = n0 + tid;
        float a = sred[tid] + sred[tid + 128] + Bscore[l];
        float s = 1.0f / (1.0f + expf(-a));
        g_f[l * NTOK + n] = s * mask[(size_t)n * LL + l];
    }
}

// ---------------------------------------------------------------------------
// K2: per (64-token tile, capsule pair, l): V = mu_in @ Wvote + Bvote.
// M=64, N=128, K=64. Block 256 (8 warps), warp = M32 x N32. float2-pair SMEM.
// grid (16, 8, 32) = 4096 CTAs, ~104 KB SMEM -> 2 CTAs/SM.
// ---------------------------------------------------------------------------
#define KP2 76    // A2 row stride (float2): 64 k + 12 pad
#define NP2 132   // B2 row stride (float2): 128 n + 4 pad
#define K2_F2 (64 * KP2 + 64 * NP2)
#define K2_DYN (K2_F2 * 8 + 128 * 4)
__global__ __launch_bounds__(256) void k2h(const float* __restrict__ Wvote,
                                           const float* __restrict__ Bvote) {
    float2* A2 = (float2*)smbase;             // [64][KP2]
    float2* B2 = A2 + 64 * KP2;               // [64][NP2]  row = i, col = kl*64+o
    float* bias = (float*)(smbase + K2_F2 * 8);   // [128]

    const int n0 = blockIdx.x * 64, kg = blockIdx.y, l = blockIdx.z;
    const int tid = threadIdx.x, wid = tid >> 5, lane = tid & 31;
    const int g = lane >> 2, tig = lane & 3;
    const int wm = wid & 1, wn = wid >> 1;   // warp tile: M32 (wm), N32 (wn)

    // stage A: thread (m = tid>>2, iq = (tid&3)*16) loads 16 i's
    {
        int m = tid >> 2, iq = (tid & 3) * 16;
        const float* mp = g_mu + ((size_t)l * NTOK + n0 + m) * IND + iq;
        float2* Ar = A2 + m * KP2 + iq;
#pragma unroll
        for (int j = 0; j < 4; j++) {
            float4 v = *(const float4*)(mp + 4 * j);
            float2 p0 = hl(v.x), p1 = hl(v.y), p2 = hl(v.z), p3 = hl(v.w);
            *(float4*)(Ar + 4 * j) = make_float4(p0.x, p0.y, p1.x, p1.y);
            *(float4*)(Ar + 4 * j + 2) = make_float4(p2.x, p2.y, p3.x, p3.y);
        }
    }
    // stage B: thread (kl = tid>>7, i = (tid>>1)&63, oq = (tid&1)*32) loads 32 o's
    {
        int kl = tid >> 7, i = (tid >> 1) & 63, oq = (tid & 1) * 32;
        const float* wv = Wvote + ((size_t)(l * NOUT + kg * 2 + kl) * IND + i) * OUTD + oq;
        float2* Br = B2 + i * NP2 + kl * 64 + oq;
#pragma unroll
        for (int j = 0; j < 8; j++) {
            float4 v = *(const float4*)(wv + 4 * j);
            float2 p0 = hl(v.x), p1 = hl(v.y), p2 = hl(v.z), p3 = hl(v.w);
            *(float4*)(Br + 4 * j) = make_float4(p0.x, p0.y, p1.x, p1.y);
            *(float4*)(Br + 4 * j + 2) = make_float4(p2.x, p2.y, p3.x, p3.y);
        }
    }
    if (tid < 128)
        bias[tid] = Bvote[(size_t)(l * NOUT + kg * 2 + (tid >> 6)) * OUTD + (tid & 63)];
    __syncthreads();

    float acc[2][4][4] = {};
#pragma unroll
    for (int ks = 0; ks < 8; ks++) {
        const int kk = ks * 8;
        float2 af[2][4];
#pragma unroll
        for (int mf = 0; mf < 2; mf++) {
            int r = wm * 32 + mf * 16;
            af[mf][0] = A2[(r + g) * KP2 + kk + tig];
            af[mf][1] = A2[(r + g + 8) * KP2 + kk + tig];
            af[mf][2] = A2[(r + g) * KP2 + kk + tig + 4];
            af[mf][3] = A2[(r + g + 8) * KP2 + kk + tig + 4];
        }
#pragma unroll
        for (int nt = 0; nt < 4; nt++) {
            int n = wn * 32 + nt * 8 + g;
            float2 q0 = B2[(kk + tig) * NP2 + n];
            float2 q1 = B2[(kk + tig + 4) * NP2 + n];
#pragma unroll
            for (int mf = 0; mf < 2; mf++)
                mma3(acc[mf][nt], af[mf][0], af[mf][1], af[mf][2], af[mf][3], q0, q1);
        }
    }
    // epilogue -> g_V [n][l][k][o]
#pragma unroll
    for (int mf = 0; mf < 2; mf++) {
        int r0 = wm * 32 + mf * 16 + g;
#pragma unroll
        for (int nt = 0; nt < 4; nt++) {
            int col = wn * 32 + nt * 8 + 2 * tig;      // 0..127
            int kc = kg * 2 + (col >> 6), o = col & 63;
            float b0v = bias[col], b1v = bias[col + 1];
            float2 v0, v1;
            v0.x = acc[mf][nt][0] + b0v; v0.y = acc[mf][nt][1] + b1v;
            v1.x = acc[mf][nt][2] + b0v; v1.y = acc[mf][nt][3] + b1v;
            *(float2*)(g_V + (((size_t)(n0 + r0) * LL + l) * NOUT + kc) * OUTD + o) = v0;
            *(float2*)(g_V + (((size_t)(n0 + r0 + 8) * LL + l) * NOUT + kc) * OUTD + o) = v1;
        }
    }
}

// ---------------------------------------------------------------------------
// K3: routing. One CTA per token, 512 threads (16 warps), V in SMEM.
// ---------------------------------------------------------------------------
#define K3_SMEM_FLOATS (32768 + 1024 * 3 + 512 * 2 + 32 * 2 + 16 * 5 + 16)
__global__ __launch_bounds__(512) void k3_route(
    const float* __restrict__ beta_use, const float* __restrict__ beta_ign,
    const int* __restrict__ iters_p, float* __restrict__ out) {
    float* Vs   = (float*)smbase;  // [512 pairs][64]
    float* mu   = Vs + 32768;      // [16][64]
    float* var  = mu + 1024;
    float* iv   = var + 1024;
    float* R    = iv + 1024;       // [32][16]
    float* ws   = R + 512;         // [32][16]
    float* fs   = ws + 512;        // [32]
    float* bus  = fs + 32;
    float* bis  = bus + 32;
    float* lvs  = bis + 16;
    float* lsa  = lvs + 16;
    float* aout = lsa + 16;
    float* sumw = aout + 16;
    float* sfs  = sumw + 16;

    const int n = blockIdx.x;
    const int tid = threadIdx.x;
    const int warp = tid >> 5, lane = tid & 31;

    {
        const float4* Vg4 = (const float4*)(g_V + (size_t)n * (LL * NOUT * OUTD));
        float4* Vs4 = (float4*)Vs;
#pragma unroll
        for (int i = 0; i < 16; i++) Vs4[tid + i * 512] = Vg4[tid + i * 512];
    }
    if (tid < 32) { fs[tid] = g_f[tid * NTOK + n]; bus[tid] = beta_use[tid]; }
    if (tid < 16) bis[tid] = beta_ign[tid];
    R[tid] = 1.0f / (float)NOUT;
    __syncthreads();
    if (warp == 0) {
        float v = wred(fs[lane]);
        if (lane == 0) sfs[0] = v;
    }
    __syncthreads();

    const int ITERS = *iters_p;
    for (int t = 0; t < ITERS; t++) {
        if (t > 0) {
            iv[tid]       = 1.0f / (2.0f * var[tid] + EPSF);
            iv[tid + 512] = 1.0f / (2.0f * var[tid + 512] + EPSF);
            {
                float s = logf(var[(warp << 6) + lane] + EPSF)
                        + logf(var[(warp << 6) + lane + 32] + EPSF);
                s = wred(s);
                if (lane == 0) lvs[warp] = 0.5f * s;
            }
            if (tid < 16) {
                float a = aout[tid];
                lsa[tid] = fminf(a, 0.0f) - log1pf(expf(-fabsf(a)));
            }
            __syncthreads();
            {
                const int k = tid & 15;
                const int pb = tid << 6, kb = k << 6;
                float s = 0.0f;
#pragma unroll 16
                for (int i = 0; i < 64; i++) {
                    int o = (lane + i) & 63;
                    float d = Vs[pb + o] - mu[kb + o];
                    s = fmaf(d * d, iv[kb + o], s);
                }
                float z = lsa[k] - lvs[k] - s;
                float m = z;
#pragma unroll
                for (int off = 1; off < 16; off <<= 1)
                    m = fmaxf(m, __shfl_xor_sync(0xffffffffu, m, off));
                float e = expf(z - m);
                float ssum = e;
#pragma unroll
                for (int off = 1; off < 16; off <<= 1)
                    ssum += __shfl_xor_sync(0xffffffffu, ssum, off);
                R[tid] = e / ssum;
            }
            __syncthreads();
        }
        {
            int k = warp;
            float w = fs[lane] * R[(lane << 4) + k];
            ws[(lane << 4) + k] = w;
            float wb = bus[lane] * w;
            float wr = wred(w);
            float wbr = wred(wb);
            if (lane == 0) {
                sumw[k] = wr;
                aout[k] = wbr - bis[k] * (sfs[0] - wr);
            }
        }
        __syncthreads();
        {
            const int k = warp;
            const int lh = lane >> 4;
            const int q = lane & 15;
            float4 S1 = {0.f, 0.f, 0.f, 0.f}, S2 = {0.f, 0.f, 0.f, 0.f};
#pragma unroll
            for (int li = 0; li < 16; li++) {
                int lidx = lh * 16 + li;
                float w = ws[(lidx << 4) + k];
                float4 v = *(const float4*)&Vs[(((lidx << 4) + k) << 6) + 4 * q];
                S1.x += w * v.x; S2.x += w * v.x * v.x;
                S1.y += w * v.y; S2.y += w * v.y * v.y;
                S1.z += w * v.z; S2.z += w * v.z * v.z;
                S1.w += w * v.w; S2.w += w * v.w * v.w;
            }
            S1.x += __shfl_xor_sync(0xffffffffu, S1.x, 16);
            S1.y += __shfl_xor_sync(0xffffffffu, S1.y, 16);
            S1.z += __shfl_xor_sync(0xffffffffu, S1.z, 16);
            S1.w += __shfl_xor_sync(0xffffffffu, S1.w, 16);
            S2.x += __shfl_xor_sync(0xffffffffu, S2.x, 16);
            S2.y += __shfl_xor_sync(0xffffffffu, S2.y, 16);
            S2.z += __shfl_xor_sync(0xffffffffu, S2.z, 16);
            S2.w += __shfl_xor_sync(0xffffffffu, S2.w, 16);
            if (lh == 0) {
                float invd = 1.0f / (sumw[k] + EPSF);
                float4 m4, v4;
                m4.x = S1.x * invd; m4.y = S1.y * invd;
                m4.z = S1.z * invd; m4.w = S1.w * invd;
                v4.x = fmaxf(S2.x * invd - m4.x * m4.x, 0.0f);
                v4.y = fmaxf(S2.y * invd - m4.y * m4.y, 0.0f);
                v4.z = fmaxf(S2.z * invd - m4.z * m4.z, 0.0f);
                v4.w = fmaxf(S2.w * invd - m4.w * m4.w, 0.0f);
                *(float4*)&mu[(k << 6) + 4 * q] = m4;
                *(float4*)&var[(k << 6) + 4 * q] = v4;
            }
        }
        __syncthreads();
    }
    if (tid < 16) out[n * NOUT + tid] = aout[tid];
    float* om = out + NTOK * NOUT + (size_t)n * (NOUT * OUTD);
    om[tid] = mu[tid];
    om[tid + 512] = mu[tid + 512];
}

extern "C" void kernel_launch(void* const* d_in, const int* in_sizes, int n_in,
                              void* d_out, int out_size) {
    const float* x        = (const float*)d_in[0];
    const float* mask     = (const float*)d_in[1];
    const float* Wscore   = (const float*)d_in[2];
    const float* Bscore   = (const float*)d_in[3];
    const float* Wcap     = (const float*)d_in[4];
    const float* Bcap     = (const float*)d_in[5];
    const float* Wvote    = (const float*)d_in[6];
    const float* Bvote    = (const float*)d_in[7];
    const float* beta_use = (const float*)d_in[8];
    const float* beta_ign = (const float*)d_in[9];
    const int*   iters    = (const int*)d_in[10];
    float* out = (float*)d_out;

    const size_t smem3 = (size_t)K3_SMEM_FLOATS * sizeof(float);
    cudaFuncSetAttribute(k1h, cudaFuncAttributeMaxDynamicSharedMemorySize, K1_DYN);
    cudaFuncSetAttribute(k2h, cudaFuncAttributeMaxDynamicSharedMemorySize, K2_DYN);
    cudaFuncSetAttribute(k3_route, cudaFuncAttributeMaxDynamicSharedMemorySize, (int)smem3);

    k1h<<<dim3(NTOK / 128, LL), 256, K1_DYN>>>(x, mask, Wscore, Bscore, Wcap, Bcap);
    k2h<<<dim3(NTOK / 64, NOUT / 2, LL), 256, K2_DYN>>>(Wvote, Bvote);
    k3_route<<<NTOK, 512, smem3>>>(beta_use, beta_ign, iters, out);
}

// round 14
// speedup vs baseline: 1.2979x; 1.2979x over previous
#include <cuda_runtime.h>
#include <math.h>
#include <stdint.h>

#define NTOK 1024
#define LL   32
#define DD   768
#define IND  64
#define NOUT 16
#define OUTD 64
#define EPSF 1e-8f

__device__ float g_mu[(size_t)LL * NTOK * IND];        // [l][n][i]
__device__ float g_f[LL * NTOK];                       // [l][n]
__device__ float g_V[(size_t)NTOK * LL * NOUT * OUTD]; // [n][l][k][o]

__device__ __forceinline__ float tf32r(float x) {
    uint32_t o;
    asm("cvt.rn.tf32.f32 %0, %1;" : "=r"(o) : "f"(x));
    return __uint_as_float(o);
}
__device__ __forceinline__ void mma8(float c[4], uint32_t a0, uint32_t a1,
                                     uint32_t a2, uint32_t a3,
                                     uint32_t b0, uint32_t b1) {
    asm("mma.sync.aligned.m16n8k8.row.col.f32.tf32.tf32.f32 "
        "{%0,%1,%2,%3}, {%4,%5,%6,%7}, {%8,%9}, {%0,%1,%2,%3};"
        : "+f"(c[0]), "+f"(c[1]), "+f"(c[2]), "+f"(c[3])
        : "r"(a0), "r"(a1), "r"(a2), "r"(a3), "r"(b0), "r"(b1));
}
__device__ __forceinline__ float gelu(float v) {
    return 0.5f * v * (1.0f + erff(v * 0.70710678118654752f));
}
__device__ __forceinline__ float wred(float v) {
#pragma unroll
    for (int o = 16; o; o >>= 1) v += __shfl_xor_sync(0xffffffffu, v, o);
    return v;
}

// ---------------------------------------------------------------------------
// K1: per (l, 64-token tile). Block 256 (8 warps), warp = M16 x N32.
// fp32 in SMEM, hi/lo split at fragment load. 48 K-chunks of 16,
// double-buffered, 1 sync/chunk. grid 512 CTAs -> ~3 resident CTAs/SM.
// ---------------------------------------------------------------------------
#define AS1 20   // As row stride (16 + 4 pad) - proven conflict-free
#define BS1 72   // Bs row stride (64 + 8 pad) - proven conflict-free
__global__ __launch_bounds__(256) void k1h(
    const float* __restrict__ x, const float* __restrict__ mask,
    const float* __restrict__ Wscore, const float* __restrict__ Bscore,
    const float* __restrict__ Wcap, const float* __restrict__ Bcap) {
    __shared__ __align__(16) float As[2][64 * AS1];
    __shared__ __align__(16) float Bs[2][16 * BS1];
    __shared__ float Ws[2][16];
    __shared__ float bcs[64];
    __shared__ float sred[256];

    const int l = blockIdx.y, n0 = blockIdx.x * 64;
    const int tid = threadIdx.x, wid = tid >> 5, lane = tid & 31;
    const int g = lane >> 2, tig = lane & 3;
    const int wm = wid & 3, wn = wid >> 2;            // warp tile: M16, N32
    const int am = tid & 63, aq = tid >> 6;           // A staging: row, k-quad
    const int bk = tid >> 4, bcol4 = (tid & 15) * 4;  // B staging

    if (tid < 64) bcs[tid] = Bcap[l * IND + tid];

    const float* xl = x + (size_t)(n0 + am) * (LL * DD) + (size_t)l * DD + aq * 4;
    const float* wc = Wcap + (size_t)l * DD * IND;

    // stage chunk 0 into buffer 0
    float4 a_st;
    float4 b_st;
    float w_st = 0.0f;
    a_st = *(const float4*)(xl);
    b_st = *(const float4*)(wc + (size_t)bk * IND + bcol4);
    if (tid < 16) w_st = Wscore[l * DD + tid];
    *(float4*)(As[0] + am * AS1 + aq * 4) = a_st;
    Bs[0][bk * BS1 + bcol4 + 0] = b_st.x;
    Bs[0][bk * BS1 + bcol4 + 1] = b_st.y;
    Bs[0][bk * BS1 + bcol4 + 2] = b_st.z;
    Bs[0][bk * BS1 + bcol4 + 3] = b_st.w;
    if (tid < 16) Ws[0][tid] = w_st;
    __syncthreads();

    float acc[4][4] = {};
    float sacc = 0.0f;

    for (int c = 0; c < 48; c++) {
        const int buf = c & 1;
        // score partial from full-fp32 regs of chunk c (4 k's per thread)
        {
            int kb = aq * 4;
            sacc += a_st.x * Ws[buf][kb + 0] + a_st.y * Ws[buf][kb + 1]
                  + a_st.z * Ws[buf][kb + 2] + a_st.w * Ws[buf][kb + 3];
        }
        // prefetch chunk c+1 into regs
        if (c + 1 < 48) {
            int k0 = (c + 1) * 16;
            a_st = *(const float4*)(xl + k0);
            b_st = *(const float4*)(wc + (size_t)(k0 + bk) * IND + bcol4);
            if (tid < 16) w_st = Wscore[l * DD + k0 + tid];
        }
        // mma on buffer buf: 2 k8 steps, 3 compensated passes, warp tile M16xN32
#pragma unroll
        for (int ks = 0; ks < 2; ks++) {
            const int kk = ks * 8;
            uint32_t ah[4], al[4];
            {
                int r = wm * 16;
                float v0 = As[buf][(r + g) * AS1 + kk + tig];
                float v1 = As[buf][(r + g + 8) * AS1 + kk + tig];
                float v2 = As[buf][(r + g) * AS1 + kk + tig + 4];
                float v3 = As[buf][(r + g + 8) * AS1 + kk + tig + 4];
                float h0 = tf32r(v0), h1 = tf32r(v1), h2 = tf32r(v2), h3 = tf32r(v3);
                ah[0] = __float_as_uint(h0); al[0] = __float_as_uint(tf32r(v0 - h0));
                ah[1] = __float_as_uint(h1); al[1] = __float_as_uint(tf32r(v1 - h1));
                ah[2] = __float_as_uint(h2); al[2] = __float_as_uint(tf32r(v2 - h2));
                ah[3] = __float_as_uint(h3); al[3] = __float_as_uint(tf32r(v3 - h3));
            }
#pragma unroll
            for (int nt = 0; nt < 4; nt++) {
                int n = wn * 32 + nt * 8 + g;
                float bv0 = Bs[buf][(kk + tig) * BS1 + n];
                float bv1 = Bs[buf][(kk + tig + 4) * BS1 + n];
                float bh0f = tf32r(bv0), bh1f = tf32r(bv1);
                uint32_t bh0 = __float_as_uint(bh0f), bh1 = __float_as_uint(bh1f);
                uint32_t bl0 = __float_as_uint(tf32r(bv0 - bh0f));
                uint32_t bl1 = __float_as_uint(tf32r(bv1 - bh1f));
                mma8(acc[nt], al[0], al[1], al[2], al[3], bh0, bh1);
                mma8(acc[nt], ah[0], ah[1], ah[2], ah[3], bl0, bl1);
                mma8(acc[nt], ah[0], ah[1], ah[2], ah[3], bh0, bh1);
            }
        }
        // store chunk c+1 into the other buffer (its readers synced at c-1)
        if (c + 1 < 48) {
            const int nb = buf ^ 1;
            *(float4*)(As[nb] + am * AS1 + aq * 4) = a_st;
            Bs[nb][bk * BS1 + bcol4 + 0] = b_st.x;
            Bs[nb][bk * BS1 + bcol4 + 1] = b_st.y;
            Bs[nb][bk * BS1 + bcol4 + 2] = b_st.z;
            Bs[nb][bk * BS1 + bcol4 + 3] = b_st.w;
            if (tid < 16) Ws[nb][tid] = w_st;
        }
        __syncthreads();
    }
    // epilogue: bias + GELU -> g_mu  (rows wm*16+g, +8; cols wn*32..+31)
    {
        int r0 = wm * 16 + g;
#pragma unroll
        for (int nt = 0; nt < 4; nt++) {
            int col = wn * 32 + nt * 8 + 2 * tig;
            float b0v = bcs[col], b1v = bcs[col + 1];
            float2 v0, v1;
            v0.x = gelu(acc[nt][0] + b0v);
            v0.y = gelu(acc[nt][1] + b1v);
            v1.x = gelu(acc[nt][2] + b0v);
            v1.y = gelu(acc[nt][3] + b1v);
            *(float2*)(g_mu + ((size_t)l * NTOK + n0 + r0) * IND + col) = v0;
            *(float2*)(g_mu + ((size_t)l * NTOK + n0 + r0 + 8) * IND + col) = v1;
        }
    }
    // score: combine the four k-quarter partials
    sred[tid] = sacc;
    __syncthreads();
    if (tid < 64) {
        int n = n0 + tid;
        float a = sred[tid] + sred[tid + 64] + sred[tid + 128] + sred[tid + 192]
                + Bscore[l];
        float s = 1.0f / (1.0f + expf(-a));
        g_f[l * NTOK + n] = s * mask[(size_t)n * LL + l];
    }
}

// ---------------------------------------------------------------------------
// K2 (proven): per (128-token tile, capsule pair, l): V = mu_in @ Wvote + Bvote.
// M=128, N=128, K=64. Block 256. Warp: M32, N64. ~70 KB SMEM, 3 CTAs/SM.
// Wvote loads float4-coalesced.
// ---------------------------------------------------------------------------
#define AS2 68    // A row stride (64 + 4)
#define BS2 136   // B row stride (128 + 8)
#define K2_DYN ((128 * AS2 + 64 * BS2 + 128) * 4)
__global__ __launch_bounds__(256) void k2h(const float* __restrict__ Wvote,
                                           const float* __restrict__ Bvote) {
    extern __shared__ __align__(16) float s2[];
    float* As = s2;                      // [128][AS2] fp32
    float* Bs = As + 128 * AS2;          // [64][BS2]  (row=i, col=kl*64+o)
    float* bias = Bs + 64 * BS2;         // [128]

    const int n0 = blockIdx.x * 128, kg = blockIdx.y, l = blockIdx.z;
    const int tid = threadIdx.x, wid = tid >> 5, lane = tid & 31;
    const int g = lane >> 2, tig = lane & 3;

    {
        int m = tid & 127, half = tid >> 7;
        const float* mp = g_mu + ((size_t)l * NTOK + n0 + m) * IND + half * 32;
#pragma unroll
        for (int j = 0; j < 8; j++)
            *(float4*)(As + m * AS2 + half * 32 + j * 4) = *(const float4*)(mp + j * 4);
    }
    {   // coalesced Wvote: thread (kl, i0, o4) loads rows i = i0 + 8j
        int kl = tid >> 7, i0 = (tid >> 4) & 7, o4 = (tid & 15) * 4;
        const float* wv = Wvote + (size_t)(l * NOUT + kg * 2 + kl) * IND * OUTD;
#pragma unroll
        for (int j = 0; j < 8; j++) {
            int i = i0 + j * 8;
            float4 v = *(const float4*)(wv + (size_t)i * OUTD + o4);
            *(float4*)(Bs + i * BS2 + kl * 64 + o4) = v;
        }
    }
    if (tid < 128)
        bias[tid] = Bvote[(size_t)(l * NOUT + kg * 2 + (tid >> 6)) * OUTD + (tid & 63)];
    __syncthreads();

    const int mrow0 = (wid & 3) * 32, nhalf = wid >> 2;
    float acc[2][8][4] = {};
#pragma unroll
    for (int ks = 0; ks < 8; ks++) {
        const int kk = ks * 8;
        uint32_t ah[2][4], al[2][4];
#pragma unroll
        for (int mf = 0; mf < 2; mf++) {
            int r = mrow0 + mf * 16;
            float v0 = As[(r + g) * AS2 + kk + tig];
            float v1 = As[(r + g + 8) * AS2 + kk + tig];
            float v2 = As[(r + g) * AS2 + kk + tig + 4];
            float v3 = As[(r + g + 8) * AS2 + kk + tig + 4];
            float h0 = tf32r(v0), h1 = tf32r(v1), h2 = tf32r(v2), h3 = tf32r(v3);
            ah[mf][0] = __float_as_uint(h0); al[mf][0] = __float_as_uint(tf32r(v0 - h0));
            ah[mf][1] = __float_as_uint(h1); al[mf][1] = __float_as_uint(tf32r(v1 - h1));
            ah[mf][2] = __float_as_uint(h2); al[mf][2] = __float_as_uint(tf32r(v2 - h2));
            ah[mf][3] = __float_as_uint(h3); al[mf][3] = __float_as_uint(tf32r(v3 - h3));
        }
#pragma unroll
        for (int nt = 0; nt < 8; nt++) {
            int n = nhalf * 64 + nt * 8 + g;
            float bv0 = Bs[(kk + tig) * BS2 + n];
            float bv1 = Bs[(kk + tig + 4) * BS2 + n];
            float bh0f = tf32r(bv0), bh1f = tf32r(bv1);
            uint32_t bh0 = __float_as_uint(bh0f), bh1 = __float_as_uint(bh1f);
            uint32_t bl0 = __float_as_uint(tf32r(bv0 - bh0f));
            uint32_t bl1 = __float_as_uint(tf32r(bv1 - bh1f));
#pragma unroll
            for (int mf = 0; mf < 2; mf++) {
                mma8(acc[mf][nt], al[mf][0], al[mf][1], al[mf][2], al[mf][3], bh0, bh1);
                mma8(acc[mf][nt], ah[mf][0], ah[mf][1], ah[mf][2], ah[mf][3], bl0, bl1);
                mma8(acc[mf][nt], ah[mf][0], ah[mf][1], ah[mf][2], ah[mf][3], bh0, bh1);
            }
        }
    }
    const int kc = kg * 2 + nhalf;
#pragma unroll
    for (int mf = 0; mf < 2; mf++) {
        int r0 = mrow0 + mf * 16 + g;
#pragma unroll
        for (int nt = 0; nt < 8; nt++) {
            int col = nt * 8 + 2 * tig;
            float b0v = bias[nhalf * 64 + col], b1v = bias[nhalf * 64 + col + 1];
            float2 v0, v1;
            v0.x = acc[mf][nt][0] + b0v; v0.y = acc[mf][nt][1] + b1v;
            v1.x = acc[mf][nt][2] + b0v; v1.y = acc[mf][nt][3] + b1v;
            *(float2*)(g_V + (((size_t)(n0 + r0) * LL + l) * NOUT + kc) * OUTD + col) = v0;
            *(float2*)(g_V + (((size_t)(n0 + r0 + 8) * LL + l) * NOUT + kc) * OUTD + col) = v1;
        }
    }
}

// ---------------------------------------------------------------------------
// K3 (proven): routing. One CTA per token, 512 threads (16 warps), V in SMEM.
// z-pass: thread per (l,k) pair, straight-line FMA, half-warp shfl softmax.
// ---------------------------------------------------------------------------
#define K3_SMEM_FLOATS (32768 + 1024 * 3 + 512 * 2 + 32 * 2 + 16 * 5 + 16)
__global__ __launch_bounds__(512) void k3_route(
    const float* __restrict__ beta_use, const float* __restrict__ beta_ign,
    const int* __restrict__ iters_p, float* __restrict__ out) {
    extern __shared__ __align__(16) float sm[];
    float* Vs   = sm;              // [512 pairs][64]
    float* mu   = Vs + 32768;      // [16][64]
    float* var  = mu + 1024;
    float* iv   = var + 1024;
    float* R    = iv + 1024;       // [32][16]
    float* ws   = R + 512;         // [32][16]
    float* fs   = ws + 512;        // [32]
    float* bus  = fs + 32;
    float* bis  = bus + 32;
    float* lvs  = bis + 16;
    float* lsa  = lvs + 16;
    float* aout = lsa + 16;
    float* sumw = aout + 16;
    float* sfs  = sumw + 16;

    const int n = blockIdx.x;
    const int tid = threadIdx.x;
    const int warp = tid >> 5, lane = tid & 31;

    {
        const float4* Vg4 = (const float4*)(g_V + (size_t)n * (LL * NOUT * OUTD));
        float4* Vs4 = (float4*)Vs;
#pragma unroll
        for (int i = 0; i < 16; i++) Vs4[tid + i * 512] = Vg4[tid + i * 512];
    }
    if (tid < 32) { fs[tid] = g_f[tid * NTOK + n]; bus[tid] = beta_use[tid]; }
    if (tid < 16) bis[tid] = beta_ign[tid];
    R[tid] = 1.0f / (float)NOUT;
    __syncthreads();
    if (warp == 0) {
        float v = wred(fs[lane]);
        if (lane == 0) sfs[0] = v;
    }
    __syncthreads();

    const int ITERS = *iters_p;
    for (int t = 0; t < ITERS; t++) {
        if (t > 0) {
            iv[tid]       = 1.0f / (2.0f * var[tid] + EPSF);
            iv[tid + 512] = 1.0f / (2.0f * var[tid + 512] + EPSF);
            {
                float s = logf(var[(warp << 6) + lane] + EPSF)
                        + logf(var[(warp << 6) + lane + 32] + EPSF);
                s = wred(s);
                if (lane == 0) lvs[warp] = 0.5f * s;
            }
            if (tid < 16) {
                float a = aout[tid];
                lsa[tid] = fminf(a, 0.0f) - log1pf(expf(-fabsf(a)));
            }
            __syncthreads();
            {
                const int k = tid & 15;
                const int pb = tid << 6, kb = k << 6;
                float s = 0.0f;
#pragma unroll 16
                for (int i = 0; i < 64; i++) {
                    int o = (lane + i) & 63;
                    float d = Vs[pb + o] - mu[kb + o];
                    s = fmaf(d * d, iv[kb + o], s);
                }
                float z = lsa[k] - lvs[k] - s;
                float m = z;
#pragma unroll
                for (int off = 1; off < 16; off <<= 1)
                    m = fmaxf(m, __shfl_xor_sync(0xffffffffu, m, off));
                float e = expf(z - m);
                float ssum = e;
#pragma unroll
                for (int off = 1; off < 16; off <<= 1)
                    ssum += __shfl_xor_sync(0xffffffffu, ssum, off);
                R[tid] = e / ssum;
            }
            __syncthreads();
        }
        {
            int k = warp;
            float w = fs[lane] * R[(lane << 4) + k];
            ws[(lane << 4) + k] = w;
            float wb = bus[lane] * w;
            float wr = wred(w);
            float wbr = wred(wb);
            if (lane == 0) {
                sumw[k] = wr;
                aout[k] = wbr - bis[k] * (sfs[0] - wr);
            }
        }
        __syncthreads();
        {
            const int k = warp;
            const int lh = lane >> 4;
            const int q = lane & 15;
            float4 S1 = {0.f, 0.f, 0.f, 0.f}, S2 = {0.f, 0.f, 0.f, 0.f};
#pragma unroll
            for (int li = 0; li < 16; li++) {
                int lidx = lh * 16 + li;
                float w = ws[(lidx << 4) + k];
                float4 v = *(const float4*)&Vs[(((lidx << 4) + k) << 6) + 4 * q];
                S1.x += w * v.x; S2.x += w * v.x * v.x;
                S1.y += w * v.y; S2.y += w * v.y * v.y;
                S1.z += w * v.z; S2.z += w * v.z * v.z;
                S1.w += w * v.w; S2.w += w * v.w * v.w;
            }
            S1.x += __shfl_xor_sync(0xffffffffu, S1.x, 16);
            S1.y += __shfl_xor_sync(0xffffffffu, S1.y, 16);
            S1.z += __shfl_xor_sync(0xffffffffu, S1.z, 16);
            S1.w += __shfl_xor_sync(0xffffffffu, S1.w, 16);
            S2.x += __shfl_xor_sync(0xffffffffu, S2.x, 16);
            S2.y += __shfl_xor_sync(0xffffffffu, S2.y, 16);
            S2.z += __shfl_xor_sync(0xffffffffu, S2.z, 16);
            S2.w += __shfl_xor_sync(0xffffffffu, S2.w, 16);
            if (lh == 0) {
                float invd = 1.0f / (sumw[k] + EPSF);
                float4 m4, v4;
                m4.x = S1.x * invd; m4.y = S1.y * invd;
                m4.z = S1.z * invd; m4.w = S1.w * invd;
                v4.x = fmaxf(S2.x * invd - m4.x * m4.x, 0.0f);
                v4.y = fmaxf(S2.y * invd - m4.y * m4.y, 0.0f);
                v4.z = fmaxf(S2.z * invd - m4.z * m4.z, 0.0f);
                v4.w = fmaxf(S2.w * invd - m4.w * m4.w, 0.0f);
                *(float4*)&mu[(k << 6) + 4 * q] = m4;
                *(float4*)&var[(k << 6) + 4 * q] = v4;
            }
        }
        __syncthreads();
    }
    if (tid < 16) out[n * NOUT + tid] = aout[tid];
    float* om = out + NTOK * NOUT + (size_t)n * (NOUT * OUTD);
    om[tid] = mu[tid];
    om[tid + 512] = mu[tid + 512];
}

extern "C" void kernel_launch(void* const* d_in, const int* in_sizes, int n_in,
                              void* d_out, int out_size) {
    const float* x        = (const float*)d_in[0];
    const float* mask     = (const float*)d_in[1];
    const float* Wscore   = (const float*)d_in[2];
    const float* Bscore   = (const float*)d_in[3];
    const float* Wcap     = (const float*)d_in[4];
    const float* Bcap     = (const float*)d_in[5];
    const float* Wvote    = (const float*)d_in[6];
    const float* Bvote    = (const float*)d_in[7];
    const float* beta_use = (const float*)d_in[8];
    const float* beta_ign = (const float*)d_in[9];
    const int*   iters    = (const int*)d_in[10];
    float* out = (float*)d_out;

    const size_t smem3 = (size_t)K3_SMEM_FLOATS * sizeof(float);
    cudaFuncSetAttribute(k2h, cudaFuncAttributeMaxDynamicSharedMemorySize, K2_DYN);
    cudaFuncSetAttribute(k3_route, cudaFuncAttributeMaxDynamicSharedMemorySize, (int)smem3);

    k1h<<<dim3(NTOK / 64, LL), 256>>>(x, mask, Wscore, Bscore, Wcap, Bcap);
    k2h<<<dim3(NTOK / 128, NOUT / 2, LL), 256, K2_DYN>>>(Wvote, Bvote);
    k3_route<<<NTOK, 512, smem3>>>(beta_use, beta_ign, iters, out);
}